// round 10
// baseline (speedup 1.0000x reference)
#include <cuda_runtime.h>
#include <cuda_bf16.h>
#include <cstdint>

#define B 4096
#define D 128
#define TEMP 100.0f
#define NT 512
#define NBLK 16                        // 256-row blocks
#define NTILES (NBLK * (NBLK + 1) / 2) // 136
#define BS (B * 64)                    // elems per plane (B rows x 128B)

// smem map
#define SM_A     0                     // A: 2 planes x 32768
#define SM_B     65536                 // 2 bufs x (2 planes x 4096) = 16384
#define SM_META  81920                 // sqr[256] sqc[256] labr[256] labc[256]
#define SM_COLD  86016                 // colD[2][16][32] = 4096
#define SM_COLN  90112                 // colN[2][16][32] = 4096
#define SM_MB    94208                 // mbarA, mbB0, mbB1
#define SMEM_SZ  94336

// gmem: 2 planes (h0,h1), each row 128B, SW128 pre-swizzled per 1024B block
__device__ __align__(1024) __nv_bfloat16 g_xs[2 * BS];
__device__ __align__(16) float g_sq[B];
__device__ int   g_lab[B];
__device__ float g_pd[NBLK][B];
__device__ float g_pn[NBLK][B];
__device__ float g_part[16];
__device__ unsigned int g_cnt;

__device__ __forceinline__ uint32_t smem_to_u32(const void* p) {
    uint32_t a;
    asm("{ .reg .u64 t; cvta.to.shared.u64 t, %1; cvt.u32.u64 %0, t; }"
        : "=r"(a) : "l"(p));
    return a;
}
__device__ __forceinline__ uint32_t swz(uint32_t x) { return x ^ ((x >> 3) & 0x70); }

#define MBAR_INIT(m, c) \
    asm volatile("mbarrier.init.shared.b64 [%0], %1;" \
                 :: "r"((uint32_t)(m)), "r"((uint32_t)(c)) : "memory")
#define MBAR_EXPECT(m, n) \
    asm volatile("mbarrier.arrive.expect_tx.shared.b64 _, [%0], %1;" \
                 :: "r"((uint32_t)(m)), "r"((uint32_t)(n)) : "memory")
#define MBAR_WAIT(m, par) do { \
    uint32_t _m = (uint32_t)(m); uint32_t _p = (uint32_t)(par); uint32_t _d; \
    asm volatile("{\n\t.reg .pred p;\n\t" \
        "mbarrier.try_wait.parity.acquire.cta.shared::cta.b64 p, [%1], %2;\n\t" \
        "selp.b32 %0, 1, 0, p;\n\t}" : "=r"(_d) : "r"(_m), "r"(_p) : "memory"); \
    if (!_d) { \
        asm volatile("{\n\t.reg .pred P1;\n\t" \
            "WL_%=:\n\t" \
            "mbarrier.try_wait.parity.acquire.cta.shared::cta.b64 P1, [%0], %1, 0x989680;\n\t" \
            "@P1 bra.uni WD_%=;\n\tbra.uni WL_%=;\n\tWD_%=:\n\t}" \
            :: "r"(_m), "r"(_p) : "memory"); \
    } } while (0)

__device__ __forceinline__ void bulk_cp(uint32_t dst, const void* src,
                                        uint32_t bytes, uint32_t mbar) {
    asm volatile(
        "cp.async.bulk.shared::cluster.global.mbarrier::complete_tx::bytes "
        "[%0], [%1], %2, [%3];"
        :: "r"(dst), "l"(src), "r"(bytes), "r"(mbar) : "memory");
}

#define LDSM_X4(r0, r1, r2, r3, addr) \
    asm volatile("ldmatrix.sync.aligned.m8n8.x4.shared.b16 {%0,%1,%2,%3}, [%4];" \
                 : "=r"(r0), "=r"(r1), "=r"(r2), "=r"(r3) : "r"(addr))
#define MMA16816(c, a, b0, b1) \
    asm volatile("mma.sync.aligned.m16n8k16.row.col.f32.bf16.bf16.f32 " \
                 "{%0,%1,%2,%3}, {%4,%5,%6,%7}, {%8,%9}, {%0,%1,%2,%3};" \
                 : "+f"((c)[0]), "+f"((c)[1]), "+f"((c)[2]), "+f"((c)[3]) \
                 : "r"((a)[0]), "r"((a)[1]), "r"((a)[2]), "r"((a)[3]), \
                   "r"(b0), "r"(b1))

// ---------------------------------------------------------------------------
// Prep: per-row norm + label + bf16 split into pre-swizzled planes.
// ---------------------------------------------------------------------------
__global__ void snn_prep(const float* __restrict__ x, const int* __restrict__ y) {
    if (blockIdx.x == 0 && threadIdx.x == 0) g_cnt = 0;
    int gw = (blockIdx.x * blockDim.x + threadIdx.x) >> 5;
    int lane = threadIdx.x & 31;
    if (gw >= B) return;
    float4 v = reinterpret_cast<const float4*>(x + (size_t)gw * D)[lane];
    float s = v.x * v.x + v.y * v.y + v.z * v.z + v.w * v.w;
    #pragma unroll
    for (int o = 16; o; o >>= 1) s += __shfl_xor_sync(0xFFFFFFFFu, s, o);
    float vv[4] = {v.x, v.y, v.z, v.w};
    __nv_bfloat16 h[4];
    #pragma unroll
    for (int i = 0; i < 4; i++) h[i] = __float2bfloat16(vv[i]);
    int k = lane * 4;
    int hseg = k >> 6;
    uint32_t sby = swz((uint32_t)gw * 128 + (k & 63) * 2);
    char* base = reinterpret_cast<char*>(g_xs);
    *reinterpret_cast<uint2*>(base + (size_t)hseg * (BS * 2) + sby) =
        *reinterpret_cast<uint2*>(h);
    if (lane == 0) { g_sq[gw] = s; g_lab[gw] = y[gw]; }
}

// ---------------------------------------------------------------------------
// Main: 256x256 tile per CTA, triangle (136 CTAs). 16 warps, warp tile 16x32.
// 8 chunks of 32 cols; B double-buffered bulk-async (diag reads A in place).
// ---------------------------------------------------------------------------
__global__ void __launch_bounds__(NT, 1)
snn_main() {
    extern __shared__ char smem[];
    uint32_t sb = smem_to_u32(smem);
    const int tid = threadIdx.x;
    const int lane = tid & 31;
    const int wid = tid >> 5;
    const int grp = lane >> 3, l7 = lane & 7;
    const float NEGC = -1.4426950408889634f / TEMP;
    const float C2   = 2.0f * 1.4426950408889634f / TEMP;

    int t = blockIdx.x, bi = 0;
    while (t >= NBLK - bi) { t -= NBLK - bi; bi++; }
    const int bj = bi + t;
    const bool diag = (bi == bj);
    const int row0 = bi * 256, col0 = bj * 256;

    const uint32_t mbA = sb + SM_MB;
    if (tid == 0) {
        MBAR_INIT(mbA, 1);
        MBAR_INIT(mbA + 8, 1);
        MBAR_INIT(mbA + 16, 1);
    }
    __syncthreads();

    const char* gx = reinterpret_cast<const char*>(g_xs);
    if (tid == 0) {
        MBAR_EXPECT(mbA, 65536);
        #pragma unroll
        for (int s = 0; s < 2; s++)
            bulk_cp(sb + SM_A + s * 32768,
                    gx + (size_t)s * (BS * 2) + (size_t)row0 * 128, 32768, mbA);
        if (!diag) {
            #pragma unroll
            for (int c0 = 0; c0 < 2; c0++) {          // chunks 0 and 1
                uint32_t mb = mbA + 8 + c0 * 8;
                MBAR_EXPECT(mb, 8192);
                #pragma unroll
                for (int s = 0; s < 2; s++)
                    bulk_cp(sb + SM_B + (uint32_t)(c0 * 8192 + s * 4096),
                            gx + (size_t)s * (BS * 2)
                               + (size_t)(col0 + c0 * 32) * 128, 4096, mb);
            }
        }
    }

    float* sqr  = reinterpret_cast<float*>(smem + SM_META);
    float* sqc  = sqr + 256;
    int*   labr = reinterpret_cast<int*>(sqc + 256);
    int*   labc = labr + 256;
    if (tid < 256) { sqr[tid] = g_sq[row0 + tid] * NEGC;  labr[tid] = g_lab[row0 + tid]; }
    else { sqc[tid - 256] = g_sq[col0 + tid - 256] * NEGC;
           labc[tid - 256] = g_lab[col0 + tid - 256]; }
    __syncthreads();

    // fragment addressing (R4/R7-verified recipe, adapted to 16x32 warp tile)
    const uint32_t pa = (uint32_t)((wid * 16 + (grp & 1) * 8 + l7) * 128 + (grp >> 1) * 16);
    const uint32_t pb = (uint32_t)(((grp >> 1) * 8 + l7) * 128 + (grp & 1) * 16);
    const int rbase = lane >> 2, cpair = (lane & 3) * 2;

    const float* csq = diag ? sqr : sqc;
    const int*   clb = diag ? labr : labc;

    float ci[2]; int labi[2];
    ci[0] = sqr[wid * 16 + rbase];      labi[0] = labr[wid * 16 + rbase];
    ci[1] = sqr[wid * 16 + 8 + rbase];  labi[1] = labr[wid * 16 + 8 + rbase];
    float rs_d[2] = {0.f, 0.f}, rs_n[2] = {0.f, 0.f};

    float* colD = reinterpret_cast<float*>(smem + SM_COLD);
    float* colN = reinterpret_cast<float*>(smem + SM_COLN);

    MBAR_WAIT(mbA, 0);

    for (int c = 0; c < 8; c++) {
        uint32_t bpl, bstr;
        if (diag) { bpl = sb + SM_A + (uint32_t)(c * 4096); bstr = 32768; }
        else {
            MBAR_WAIT(mbA + 8 + (uint32_t)((c & 1) * 8), (c >> 1) & 1);
            bpl = sb + SM_B + (uint32_t)((c & 1) * 8192); bstr = 4096;
        }

        float acc[4][4];
        #pragma unroll
        for (int nt = 0; nt < 4; nt++)
            #pragma unroll
            for (int e = 0; e < 4; e++) acc[nt][e] = 0.f;

        #pragma unroll
        for (int ks = 0; ks < 8; ks++) {
            const uint32_t koff = (ks & 3) * 32;
            const uint32_t ka = sb + SM_A + (ks >> 2) * 32768;
            const uint32_t kb = bpl + (ks >> 2) * bstr;
            uint32_t a[4], b0[4], b1[4];
            LDSM_X4(a[0], a[1], a[2], a[3], ka + swz(pa + koff));
            LDSM_X4(b0[0], b0[1], b0[2], b0[3], kb + swz(pb + koff));
            LDSM_X4(b1[0], b1[1], b1[2], b1[3], kb + swz(pb + 2048 + koff));
            MMA16816(acc[0], a, b0[0], b0[1]);
            MMA16816(acc[1], a, b0[2], b0[3]);
            MMA16816(acc[2], a, b1[0], b1[1]);
            MMA16816(acc[3], a, b1[2], b1[3]);
        }

        float cj[8]; int labjt[8];
        #pragma unroll
        for (int k = 0; k < 8; k++) {
            int cloc = c * 32 + (k >> 1) * 8 + cpair + (k & 1);
            cj[k] = csq[cloc];  labjt[k] = clb[cloc];
        }

        if (diag) {
            #pragma unroll
            for (int nt = 0; nt < 4; nt++)
                #pragma unroll
                for (int e = 0; e < 4; e++) {
                    int i = e >> 1, k = nt * 2 + (e & 1);
                    float arg = fmaf(acc[nt][e], C2, ci[i] + cj[k]);
                    arg = fminf(arg, 0.f);
                    float ev = exp2f(arg);
                    int rl   = wid * 16 + i * 8 + rbase;
                    int cloc = c * 32 + nt * 8 + cpair + (e & 1);
                    bool self = (rl == cloc);
                    if (self) ev = 1.f;
                    float nv = (labi[i] == labjt[k] && !self) ? ev : 0.f;
                    rs_d[i] += ev;  rs_n[i] += nv;
                }
        } else {
            float cs_d[8] = {0,0,0,0,0,0,0,0}, cs_n[8] = {0,0,0,0,0,0,0,0};
            #pragma unroll
            for (int nt = 0; nt < 4; nt++)
                #pragma unroll
                for (int e = 0; e < 4; e++) {
                    int i = e >> 1, k = nt * 2 + (e & 1);
                    float arg = fmaf(acc[nt][e], C2, ci[i] + cj[k]);
                    arg = fminf(arg, 0.f);
                    float ev = exp2f(arg);
                    float nv = (labi[i] == labjt[k]) ? ev : 0.f;
                    rs_d[i] += ev;  rs_n[i] += nv;
                    cs_d[k] += ev;  cs_n[k] += nv;
                }
            #pragma unroll
            for (int k = 0; k < 8; k++) {
                cs_d[k] += __shfl_xor_sync(0xFFFFFFFFu, cs_d[k], 4);
                cs_d[k] += __shfl_xor_sync(0xFFFFFFFFu, cs_d[k], 8);
                cs_d[k] += __shfl_xor_sync(0xFFFFFFFFu, cs_d[k], 16);
                cs_n[k] += __shfl_xor_sync(0xFFFFFFFFu, cs_n[k], 4);
                cs_n[k] += __shfl_xor_sync(0xFFFFFFFFu, cs_n[k], 8);
                cs_n[k] += __shfl_xor_sync(0xFFFFFFFFu, cs_n[k], 16);
            }
            const int cb = (c & 1) * 512;   // colD buffer parity
            if (lane < 4) {
                #pragma unroll
                for (int k = 0; k < 8; k++) {
                    int col = (k >> 1) * 8 + lane * 2 + (k & 1);
                    colD[cb + wid * 32 + col] = cs_d[k];
                    colN[cb + wid * 32 + col] = cs_n[k];
                }
            }
            __syncthreads();
            if (tid == 0 && c < 6) {        // issue chunk c+2 into buffer (c&1)
                uint32_t mb = mbA + 8 + (uint32_t)((c & 1) * 8);
                MBAR_EXPECT(mb, 8192);
                #pragma unroll
                for (int s = 0; s < 2; s++)
                    bulk_cp(sb + SM_B + (uint32_t)((c & 1) * 8192 + s * 4096),
                            gx + (size_t)s * (BS * 2)
                               + (size_t)(col0 + (c + 2) * 32) * 128, 4096, mb);
            }
            if (tid < 32) {
                float sd = 0.f, sn = 0.f;
                #pragma unroll
                for (int w2 = 0; w2 < 16; w2++) {
                    sd += colD[cb + w2 * 32 + tid];
                    sn += colN[cb + w2 * 32 + tid];
                }
                g_pd[bi][col0 + c * 32 + tid] = sd;
                g_pn[bi][col0 + c * 32 + tid] = sn;
            }
        }
    }

    // row sums: quad-reduce, direct store (each row owned by one warp)
    #pragma unroll
    for (int i = 0; i < 2; i++) {
        rs_d[i] += __shfl_xor_sync(0xFFFFFFFFu, rs_d[i], 1);
        rs_d[i] += __shfl_xor_sync(0xFFFFFFFFu, rs_d[i], 2);
        rs_n[i] += __shfl_xor_sync(0xFFFFFFFFu, rs_n[i], 1);
        rs_n[i] += __shfl_xor_sync(0xFFFFFFFFu, rs_n[i], 2);
    }
    if ((lane & 3) == 0) {
        #pragma unroll
        for (int i = 0; i < 2; i++) {
            int r = row0 + wid * 16 + i * 8 + rbase;
            g_pd[bj][r] = rs_d[i];
            g_pn[bj][r] = rs_n[i];
        }
    }
}

// ---------------------------------------------------------------------------
// Finalize: 16 blocks; last block (counter) writes the scalar.
// ---------------------------------------------------------------------------
__global__ void snn_fin(float* __restrict__ out) {
    __shared__ float sred[256];
    int i = blockIdx.x * 256 + threadIdx.x;
    float den = 0.f, num = 0.f;
    #pragma unroll
    for (int p = 0; p < NBLK; p++) { den += g_pd[p][i]; num += g_pn[p][i]; }
    float s = logf(den) - logf(num);
    sred[threadIdx.x] = s;
    __syncthreads();
    for (int off = 128; off > 0; off >>= 1) {
        if (threadIdx.x < off) sred[threadIdx.x] += sred[threadIdx.x + off];
        __syncthreads();
    }
    if (threadIdx.x == 0) {
        g_part[blockIdx.x] = sred[0];
        __threadfence();
        unsigned int old = atomicAdd(&g_cnt, 1u);
        if (old == 15u) {
            float tot = 0.f;
            #pragma unroll
            for (int b = 0; b < 16; b++) tot += g_part[b];
            out[0] = tot / (float)B;
        }
    }
}

// ---------------------------------------------------------------------------
extern "C" void kernel_launch(void* const* d_in, const int* in_sizes, int n_in,
                              void* d_out, int out_size) {
    const float* x = (const float*)d_in[0];
    const int*   y = (const int*)d_in[1];
    float* out = (float*)d_out;

    cudaFuncSetAttribute(snn_main, cudaFuncAttributeMaxDynamicSharedMemorySize, SMEM_SZ);

    snn_prep<<<B / 8, 256>>>(x, y);
    snn_main<<<NTILES, NT, SMEM_SZ>>>();
    snn_fin<<<16, 256>>>(out);
}

// round 11
// speedup vs baseline: 1.1648x; 1.1648x over previous
#include <cuda_runtime.h>
#include <cuda_bf16.h>
#include <cstdint>

#define B 4096
#define D 128
#define TEMP 100.0f
#define NT 512
#define NBLK 16                        // 256-row blocks
#define NTILES (NBLK * (NBLK + 1) / 2) // 136
#define BS (B * 64)                    // elems per plane (B rows x 128B)

// smem map
#define SM_A     0                     // Ah0,Ah1 : 2 x 32768
#define SM_B     65536                 // 2 bufs x (Bh0,Bh1 : 2 x 8192)
#define SM_META  98304                 // sqr[256] sqc[256] labr[256] labc[256]
#define SM_RED   102400                // rowD/rowN/colD/colN [512] each
#define SM_MB    110592                // mbarA, mbarB0, mbarB1
#define SMEM_SZ  110720

// gmem: 2 planes (h0,h1), each row 128B, SW128 pre-swizzled per 1024B block
__device__ __align__(1024) __nv_bfloat16 g_xs[2 * BS];
__device__ __align__(16) float g_sq[B];
__device__ int   g_lab[B];
__device__ float g_pd[NBLK][B];
__device__ float g_pn[NBLK][B];
__device__ float g_part[16];
__device__ unsigned int g_cnt;         // 0 at load; reset by prep each launch

__device__ __forceinline__ uint32_t smem_to_u32(const void* p) {
    uint32_t a;
    asm("{ .reg .u64 t; cvta.to.shared.u64 t, %1; cvt.u32.u64 %0, t; }"
        : "=r"(a) : "l"(p));
    return a;
}
__device__ __forceinline__ uint32_t swz(uint32_t x) { return x ^ ((x >> 3) & 0x70); }

#define MBAR_INIT(m, c) \
    asm volatile("mbarrier.init.shared.b64 [%0], %1;" \
                 :: "r"((uint32_t)(m)), "r"((uint32_t)(c)) : "memory")
#define MBAR_EXPECT(m, n) \
    asm volatile("mbarrier.arrive.expect_tx.shared.b64 _, [%0], %1;" \
                 :: "r"((uint32_t)(m)), "r"((uint32_t)(n)) : "memory")
#define MBAR_WAIT(m, par) do { \
    uint32_t _m = (uint32_t)(m); uint32_t _p = (uint32_t)(par); uint32_t _d; \
    asm volatile("{\n\t.reg .pred p;\n\t" \
        "mbarrier.try_wait.parity.acquire.cta.shared::cta.b64 p, [%1], %2;\n\t" \
        "selp.b32 %0, 1, 0, p;\n\t}" : "=r"(_d) : "r"(_m), "r"(_p) : "memory"); \
    if (!_d) { \
        asm volatile("{\n\t.reg .pred P1;\n\t" \
            "WL_%=:\n\t" \
            "mbarrier.try_wait.parity.acquire.cta.shared::cta.b64 P1, [%0], %1, 0x989680;\n\t" \
            "@P1 bra.uni WD_%=;\n\tbra.uni WL_%=;\n\tWD_%=:\n\t}" \
            :: "r"(_m), "r"(_p) : "memory"); \
    } } while (0)

__device__ __forceinline__ void bulk_cp(uint32_t dst, const void* src,
                                        uint32_t bytes, uint32_t mbar) {
    asm volatile(
        "cp.async.bulk.shared::cluster.global.mbarrier::complete_tx::bytes "
        "[%0], [%1], %2, [%3];"
        :: "r"(dst), "l"(src), "r"(bytes), "r"(mbar) : "memory");
}

#define LDSM_X4(r0, r1, r2, r3, addr) \
    asm volatile("ldmatrix.sync.aligned.m8n8.x4.shared.b16 {%0,%1,%2,%3}, [%4];" \
                 : "=r"(r0), "=r"(r1), "=r"(r2), "=r"(r3) : "r"(addr))
#define MMA16816(c, a, b0, b1) \
    asm volatile("mma.sync.aligned.m16n8k16.row.col.f32.bf16.bf16.f32 " \
                 "{%0,%1,%2,%3}, {%4,%5,%6,%7}, {%8,%9}, {%0,%1,%2,%3};" \
                 : "+f"((c)[0]), "+f"((c)[1]), "+f"((c)[2]), "+f"((c)[3]) \
                 : "r"((a)[0]), "r"((a)[1]), "r"((a)[2]), "r"((a)[3]), \
                   "r"(b0), "r"(b1))

// ---------------------------------------------------------------------------
// Prep: 4 rows per warp (MLP=4 loads), norm + label + bf16 pre-swizzled split.
// ---------------------------------------------------------------------------
__global__ void snn_prep(const float* __restrict__ x, const int* __restrict__ y) {
    if (blockIdx.x == 0 && threadIdx.x == 0) g_cnt = 0;
    const int wrp = (blockIdx.x * blockDim.x + threadIdx.x) >> 5;  // 0..1023
    const int lane = threadIdx.x & 31;
    const int gw0 = wrp * 4;

    float4 v[4];
    #pragma unroll
    for (int r = 0; r < 4; r++)
        v[r] = reinterpret_cast<const float4*>(x + (size_t)(gw0 + r) * D)[lane];

    const int k = lane * 4;
    const int hseg = k >> 6;
    char* base = reinterpret_cast<char*>(g_xs) + (size_t)hseg * (BS * 2);

    #pragma unroll
    for (int r = 0; r < 4; r++) {
        float s = v[r].x * v[r].x + v[r].y * v[r].y
                + v[r].z * v[r].z + v[r].w * v[r].w;
        #pragma unroll
        for (int o = 16; o; o >>= 1) s += __shfl_xor_sync(0xFFFFFFFFu, s, o);
        __nv_bfloat16 h[4];
        h[0] = __float2bfloat16(v[r].x);  h[1] = __float2bfloat16(v[r].y);
        h[2] = __float2bfloat16(v[r].z);  h[3] = __float2bfloat16(v[r].w);
        uint32_t sby = swz((uint32_t)(gw0 + r) * 128 + (k & 63) * 2);
        *reinterpret_cast<uint2*>(base + sby) = *reinterpret_cast<uint2*>(h);
        if (lane == 0) { g_sq[gw0 + r] = s; g_lab[gw0 + r] = y[gw0 + r]; }
    }
}

// ---------------------------------------------------------------------------
// One K=128 MMA pass over a 32x32 warp tile.  (R7 verbatim)
// ---------------------------------------------------------------------------
__device__ __forceinline__ void mma_pass(float acc[2][4][4],
                                         uint32_t abase, uint32_t bbase,
                                         uint32_t bstride,
                                         uint32_t pa, uint32_t pb) {
    #pragma unroll
    for (int ks = 0; ks < 8; ks++) {
        const uint32_t koff = (ks & 3) * 32;
        const uint32_t ka = abase + (ks >> 2) * 32768;
        const uint32_t kb = bbase + (ks >> 2) * bstride;
        uint32_t a0[4], a1[4], b0[4], b1[4];
        LDSM_X4(a0[0], a0[1], a0[2], a0[3], ka + swz(pa + koff));
        LDSM_X4(a1[0], a1[1], a1[2], a1[3], ka + swz(pa + 2048 + koff));
        LDSM_X4(b0[0], b0[1], b0[2], b0[3], kb + swz(pb + koff));
        LDSM_X4(b1[0], b1[1], b1[2], b1[3], kb + swz(pb + 2048 + koff));
        MMA16816(acc[0][0], a0, b0[0], b0[1]);
        MMA16816(acc[0][1], a0, b0[2], b0[3]);
        MMA16816(acc[0][2], a0, b1[0], b1[1]);
        MMA16816(acc[0][3], a0, b1[2], b1[3]);
        MMA16816(acc[1][0], a1, b0[0], b0[1]);
        MMA16816(acc[1][1], a1, b0[2], b0[3]);
        MMA16816(acc[1][2], a1, b1[0], b1[1]);
        MMA16816(acc[1][3], a1, b1[2], b1[3]);
    }
}

// ---------------------------------------------------------------------------
// Main (R7 verbatim): 256x256 tile per CTA, triangle (136 CTAs). A resident,
// B streamed in 64-row chunks via bulk-async double buffer.
// ---------------------------------------------------------------------------
__global__ void __launch_bounds__(NT, 1)
snn_main() {
    extern __shared__ char smem[];
    uint32_t sb = smem_to_u32(smem);
    const int tid = threadIdx.x;
    const int lane = tid & 31;
    const int w = tid >> 5, wr = w >> 1, wc = w & 1;
    const int grp = lane >> 3, l7 = lane & 7;
    const float NEGC = -1.4426950408889634f / TEMP;

    int t = blockIdx.x, bi = 0;
    while (t >= NBLK - bi) { t -= NBLK - bi; bi++; }
    const int bj = bi + t;
    const bool diag = (bi == bj);
    const int row0 = bi * 256, col0 = bj * 256;

    const uint32_t mbA  = sb + SM_MB;
    const uint32_t mbB0 = sb + SM_MB + 8;
    const uint32_t mbB1 = sb + SM_MB + 16;

    if (tid == 0) { MBAR_INIT(mbA, 1); MBAR_INIT(mbB0, 1); MBAR_INIT(mbB1, 1); }
    __syncthreads();

    const char* gx = reinterpret_cast<const char*>(g_xs);
    if (tid == 0) {
        MBAR_EXPECT(mbA, 65536);
        #pragma unroll
        for (int s = 0; s < 2; s++)
            bulk_cp(sb + SM_A + s * 32768,
                    gx + (size_t)s * (BS * 2) + (size_t)row0 * 128, 32768, mbA);
        if (!diag) {
            MBAR_EXPECT(mbB0, 16384);
            #pragma unroll
            for (int s = 0; s < 2; s++)
                bulk_cp(sb + SM_B + s * 8192,
                        gx + (size_t)s * (BS * 2) + (size_t)col0 * 128, 8192, mbB0);
        }
    }

    float* sqr  = reinterpret_cast<float*>(smem + SM_META);
    float* sqc  = sqr + 256;
    int*   labr = reinterpret_cast<int*>(sqc + 256);
    int*   labc = labr + 256;
    {
        int i = tid;
        if (i < 256) { sqr[i] = g_sq[row0 + i];  labr[i] = g_lab[row0 + i]; }
        else         { sqc[i - 256] = g_sq[col0 + i - 256];
                       labc[i - 256] = g_lab[col0 + i - 256]; }
    }
    __syncthreads();

    const uint32_t pa = (uint32_t)((wr * 32 + (grp & 1) * 8 + l7) * 128 + (grp >> 1) * 16);
    const uint32_t pb = (uint32_t)((wc * 32 + (grp >> 1) * 8 + l7) * 128 + (grp & 1) * 16);
    const int rbase = lane >> 2, cpair = (lane & 3) * 2;

    float sqi[4]; int labi[4];
    #pragma unroll
    for (int i = 0; i < 4; i++) {
        int rloc = wr * 32 + (i >> 1) * 16 + (i & 1) * 8 + rbase;
        sqi[i] = sqr[rloc];  labi[i] = labr[rloc];
    }
    float rs_d[4] = {0.f, 0.f, 0.f, 0.f}, rs_n[4] = {0.f, 0.f, 0.f, 0.f};

    float* rowD = reinterpret_cast<float*>(smem + SM_RED);
    float* rowN = rowD + 512;
    float* colD = rowN + 512;
    float* colN = colD + 512;

    MBAR_WAIT(mbA, 0);

    for (int c = 0; c < 4; c++) {
        if (!diag) {
            if (tid == 0 && c < 3) {
                uint32_t mb = (c & 1) ? mbB0 : mbB1;
                MBAR_EXPECT(mb, 16384);
                #pragma unroll
                for (int s = 0; s < 2; s++)
                    bulk_cp(sb + SM_B + (uint32_t)(((c + 1) & 1) * 16384 + s * 8192),
                            gx + (size_t)s * (BS * 2)
                               + (size_t)(col0 + (c + 1) * 64) * 128, 8192, mb);
            }
            MBAR_WAIT((c & 1) ? mbB1 : mbB0, (c >> 1) & 1);
        }

        float acc[2][4][4];
        #pragma unroll
        for (int mt = 0; mt < 2; mt++)
            #pragma unroll
            for (int nt = 0; nt < 4; nt++)
                #pragma unroll
                for (int e = 0; e < 4; e++) acc[mt][nt][e] = 0.f;

        uint32_t bH, bstr;
        if (diag) { bH = sb + SM_A + c * 8192;  bstr = 32768; }
        else      { bH = sb + SM_B + (uint32_t)((c & 1) * 16384);  bstr = 8192; }
        mma_pass(acc, sb + SM_A, bH, bstr, pa, pb);

        // ---- epilogue for this 256x64 chunk ----
        float sqjt[8]; int labjt[8];
        #pragma unroll
        for (int k = 0; k < 8; k++) {
            int cloc = c * 64 + wc * 32 + (k >> 1) * 8 + cpair + (k & 1);
            sqjt[k] = diag ? sqr[cloc] : sqc[cloc];
            labjt[k] = diag ? labr[cloc] : labc[cloc];
        }
        float cs_d[8] = {0,0,0,0,0,0,0,0}, cs_n[8] = {0,0,0,0,0,0,0,0};

        #pragma unroll
        for (int mt = 0; mt < 2; mt++)
            #pragma unroll
            for (int nt = 0; nt < 4; nt++)
                #pragma unroll
                for (int e = 0; e < 4; e++) {
                    int half = e >> 1, p = e & 1;
                    int i = mt * 2 + half, k = nt * 2 + p;
                    int gi  = row0 + wr * 32 + mt * 16 + half * 8 + rbase;
                    int col = col0 + c * 64 + wc * 32 + nt * 8 + cpair + p;
                    float dist = sqi[i] + sqjt[k] - 2.f * acc[mt][nt][e];
                    dist = fmaxf(dist, 0.f);
                    float ev = exp2f(dist * NEGC);
                    bool self = (gi == col);
                    if (self) ev = 1.f;
                    float nv = (labi[i] == labjt[k] && !self) ? ev : 0.f;
                    rs_d[i] += ev;  rs_n[i] += nv;
                    cs_d[k] += ev;  cs_n[k] += nv;
                }

        if (!diag) {
            #pragma unroll
            for (int k = 0; k < 8; k++) {
                cs_d[k] += __shfl_xor_sync(0xFFFFFFFFu, cs_d[k], 4);
                cs_d[k] += __shfl_xor_sync(0xFFFFFFFFu, cs_d[k], 8);
                cs_d[k] += __shfl_xor_sync(0xFFFFFFFFu, cs_d[k], 16);
                cs_n[k] += __shfl_xor_sync(0xFFFFFFFFu, cs_n[k], 4);
                cs_n[k] += __shfl_xor_sync(0xFFFFFFFFu, cs_n[k], 8);
                cs_n[k] += __shfl_xor_sync(0xFFFFFFFFu, cs_n[k], 16);
            }
            __syncthreads();
            if (lane < 4) {
                #pragma unroll
                for (int k = 0; k < 8; k++) {
                    int cloc = wc * 32 + (k >> 1) * 8 + lane * 2 + (k & 1);
                    colD[wr * 64 + cloc] = cs_d[k];
                    colN[wr * 64 + cloc] = cs_n[k];
                }
            }
            __syncthreads();
            if (tid < 64) {
                float sd = 0.f, sn = 0.f;
                #pragma unroll
                for (int s = 0; s < 8; s++) { sd += colD[s * 64 + tid]; sn += colN[s * 64 + tid]; }
                g_pd[bi][col0 + c * 64 + tid] = sd;
                g_pn[bi][col0 + c * 64 + tid] = sn;
            }
        }
        __syncthreads();
    }

    // ---- row-sum cross-warp reduce + store ----
    #pragma unroll
    for (int i = 0; i < 4; i++) {
        rs_d[i] += __shfl_xor_sync(0xFFFFFFFFu, rs_d[i], 1);
        rs_d[i] += __shfl_xor_sync(0xFFFFFFFFu, rs_d[i], 2);
        rs_n[i] += __shfl_xor_sync(0xFFFFFFFFu, rs_n[i], 1);
        rs_n[i] += __shfl_xor_sync(0xFFFFFFFFu, rs_n[i], 2);
    }
    if ((lane & 3) == 0) {
        #pragma unroll
        for (int i = 0; i < 4; i++) {
            int rloc = wr * 32 + (i >> 1) * 16 + (i & 1) * 8 + rbase;
            rowD[wc * 256 + rloc] = rs_d[i];
            rowN[wc * 256 + rloc] = rs_n[i];
        }
    }
    __syncthreads();
    if (tid < 256) {
        g_pd[bj][row0 + tid] = rowD[tid] + rowD[256 + tid];
        g_pn[bj][row0 + tid] = rowN[tid] + rowN[256 + tid];
    }
}

// ---------------------------------------------------------------------------
// Finalize (single kernel, counter-gated): per-row loss; last block writes out.
// ---------------------------------------------------------------------------
__global__ void snn_fin(float* __restrict__ out) {
    __shared__ float sred[256];
    int i = blockIdx.x * 256 + threadIdx.x;
    float den = 0.f, num = 0.f;
    #pragma unroll
    for (int p = 0; p < NBLK; p++) { den += g_pd[p][i]; num += g_pn[p][i]; }
    float s = logf(den) - logf(num);
    sred[threadIdx.x] = s;
    __syncthreads();
    for (int off = 128; off > 0; off >>= 1) {
        if (threadIdx.x < off) sred[threadIdx.x] += sred[threadIdx.x + off];
        __syncthreads();
    }
    if (threadIdx.x == 0) {
        g_part[blockIdx.x] = sred[0];
        __threadfence();
        unsigned int old = atomicAdd(&g_cnt, 1u);
        if (old == 15u) {
            float tot = 0.f;
            #pragma unroll
            for (int b = 0; b < 16; b++) tot += g_part[b];
            out[0] = tot / (float)B;
        }
    }
}

// ---------------------------------------------------------------------------
extern "C" void kernel_launch(void* const* d_in, const int* in_sizes, int n_in,
                              void* d_out, int out_size) {
    const float* x = (const float*)d_in[0];
    const int*   y = (const int*)d_in[1];
    float* out = (float*)d_out;

    cudaFuncSetAttribute(snn_main, cudaFuncAttributeMaxDynamicSharedMemorySize, SMEM_SZ);

    snn_prep<<<B / 32, 256>>>(x, y);          // 128 blocks, 4 rows per warp
    snn_main<<<NTILES, NT, SMEM_SZ>>>();
    snn_fin<<<16, 256>>>(out);
}